// round 10
// baseline (speedup 1.0000x reference)
#include <cuda_runtime.h>
#include <cuda_bf16.h>
#include <math.h>
#include <stdint.h>

#define D_DIM 128
#define N_NODES 50000
#define N_EDGES 600000
#define LN_EPS 1e-5f
#define TILE_M 64
#define NT 256

typedef unsigned int u32;

// Scratch (allocation-free rule: __device__ globals)
__device__ float g_hpre[N_NODES * D_DIM];
// Packed W fragments: [w][(ks*16+ni)*32+lane] = {hi0,hi1,lo0,lo1}
__device__ uint4 g_bfrag[3][4096];
// CSR build state. INVARIANT: g_cnt == 0 and g_bsum == 0 on entry to
// kernel_launch (static zero-init initially; offs/fill restore it each call).
__device__ int g_cnt[N_NODES];
__device__ int g_cur[N_NODES];
__device__ int g_off[N_NODES + 1];
__device__ int g_bsum[196];
__device__ int g_csr[N_EDGES];

// ---------------- smem layout (bytes) ----------------
#define SM_B1     0
#define SM_B2     512
#define SM_GAMMA  1024
#define SM_BETA   1536
#define SM_RED    2048          // 64 rows x 2 halves x float2 = 1KB
#define SM_STAGE  4096          // 64 x 128 floats = 32KB (mlp gather stage)
#define SM_AHI    (SM_STAGE + 32768)   // A frags [ks8][mi4][lane32] x 16B = 16KB
#define SM_ALO    (SM_AHI + 16384)
#define SMEM_TOTAL (SM_ALO + 16384)    // 69632 (2 CTAs/SM: 136KB < 227KB)

__device__ __forceinline__ u32 pack_bf16x2(__nv_bfloat16 lo, __nv_bfloat16 hi) {
    __nv_bfloat162 v; v.x = lo; v.y = hi;
    return *(u32*)&v;
}
__device__ __forceinline__ void split2(float a, __nv_bfloat16& hi, __nv_bfloat16& lo) {
    hi = __float2bfloat16_rn(a);
    lo = __float2bfloat16_rn(a - __bfloat162float(hi));
}
__device__ __forceinline__ void mma_bf16(float* c, const u32* a, const u32* b) {
    asm volatile(
        "mma.sync.aligned.m16n8k16.row.col.f32.bf16.bf16.f32 "
        "{%0,%1,%2,%3}, {%4,%5,%6,%7}, {%8,%9}, {%0,%1,%2,%3};"
        : "+f"(c[0]), "+f"(c[1]), "+f"(c[2]), "+f"(c[3])
        : "r"(a[0]), "r"(a[1]), "r"(a[2]), "r"(a[3]), "r"(b[0]), "r"(b[1]));
}

// ---------------------------------------------------------------------------
// W prep: 3 weight matrices -> packed hi/lo B-fragment arrays.
// ---------------------------------------------------------------------------
__global__ void wprep_kernel(const float* __restrict__ W0,
                             const float* __restrict__ W1,
                             const float* __restrict__ W2) {
    const float* Ws[3] = {W0, W1, W2};
    int w = blockIdx.x >> 3, part = blockIdx.x & 7;
    const float* W = Ws[w];
    uint4* bf = g_bfrag[w];
    for (int i = part * 1024 + threadIdx.x; i < (part + 1) * 1024; i += 256) {
        int j = i >> 7, n = i & 127;
        float w0 = W[(size_t)(2 * j)     * 128 + n];
        float w1 = W[(size_t)(2 * j + 1) * 128 + n];
        __nv_bfloat16 h0, l0, h1, l1;
        split2(w0, h0, l0);
        split2(w1, h1, l1);
        int ni = n >> 3, ks = j >> 3;
        int ln = ((n & 7) << 2) | (j & 3);
        int reg = (j >> 2) & 1;
        u32* slot = (u32*)&bf[(ks * 16 + ni) * 32 + ln];
        slot[reg]     = pack_bf16x2(h0, h1);
        slot[2 + reg] = pack_bf16x2(l0, l1);
    }
}

// ---------------------------------------------------------------------------
// CSR build (3 launches): hist -> offs -> fill
// ---------------------------------------------------------------------------
__global__ void hist_kernel(const int* __restrict__ dst) {
    int e = blockIdx.x * blockDim.x + threadIdx.x;
    if (e < N_EDGES) {
        int d = dst[e];
        atomicAdd(&g_cnt[d], 1);
        atomicAdd(&g_bsum[d >> 8], 1);   // per-256-node block sums
    }
}
__global__ void offs_kernel() {
    __shared__ int wsum[8];
    __shared__ int bpref_s;
    int b = blockIdx.x, t = threadIdx.x;
    int n = b * 256 + t;
    // block prefix: sum of g_bsum[0..b), one warp
    if (t < 32) {
        int s = 0;
        for (int i = t; i < b; i += 32) s += g_bsum[i];
        #pragma unroll
        for (int o = 16; o; o >>= 1) s += __shfl_xor_sync(0xFFFFFFFFu, s, o);
        if (t == 0) bpref_s = s;
    }
    int cnt = (n < N_NODES) ? g_cnt[n] : 0;
    if (n < N_NODES) g_cnt[n] = 0;        // restore invariant for next call
    // warp inclusive scan
    int x = cnt;
    #pragma unroll
    for (int o = 1; o < 32; o <<= 1) {
        int y = __shfl_up_sync(0xFFFFFFFFu, x, o);
        if ((t & 31) >= o) x += y;
    }
    if ((t & 31) == 31) wsum[t >> 5] = x;
    __syncthreads();
    if (t < 8) {
        int v = wsum[t];
        #pragma unroll
        for (int o = 1; o < 8; o <<= 1) {
            int y = __shfl_up_sync(0xFFu, v, o);
            if (t >= o) v += y;
        }
        wsum[t] = v;
    }
    __syncthreads();
    int wpref = (t >= 32) ? wsum[(t >> 5) - 1] : 0;
    int off = bpref_s + wpref + x - cnt;   // exclusive prefix
    if (n < N_NODES) { g_off[n] = off; g_cur[n] = off; }
    if (b == 195 && t == 255) g_off[N_NODES] = N_EDGES;
}
__global__ void fill_kernel(const int* __restrict__ src,
                            const int* __restrict__ dst) {
    int e = blockIdx.x * blockDim.x + threadIdx.x;
    if (e < 196) g_bsum[e] = 0;           // restore invariant (unused here)
    if (e < N_EDGES) {
        int p = atomicAdd(&g_cur[dst[e]], 1);
        g_csr[p] = src[e];
    }
}

// ---------------------------------------------------------------------------
// GEMM building blocks: TILE_M=64, 256 threads, 8 warps = (m 0..3, n 0..1)
// ---------------------------------------------------------------------------
__device__ __forceinline__ void frag_write(char* smem, int row, int j,
                                           float2 a) {
    __nv_bfloat16 hx, lx, hy, ly;
    split2(a.x, hx, lx);
    split2(a.y, hy, ly);
    int mi = row >> 4, ks = j >> 3;
    int ln = ((row & 7) << 2) | (j & 3);
    int reg = (((j >> 2) & 1) << 1) | ((row >> 3) & 1);
    int off = ((ks * 4 + mi) * 32 + ln) * 16 + reg * 4;
    *(u32*)(smem + SM_AHI + off) = pack_bf16x2(hx, hy);
    *(u32*)(smem + SM_ALO + off) = pack_bf16x2(lx, ly);
}

__device__ __forceinline__ void stage_A_global(char* smem,
                                               const float* __restrict__ A,
                                               int base, int nrows, int tid) {
    const float2* A2 = (const float2*)A;
    #pragma unroll 4
    for (int i = tid; i < TILE_M * 64; i += NT) {
        int row = i >> 6, j = i & 63;
        float2 a = (base + row < nrows) ? A2[(size_t)(base + row) * 64 + j]
                                        : make_float2(0.f, 0.f);
        frag_write(smem, row, j, a);
    }
}

__device__ __forceinline__ void stage_A_smem(char* smem, int tid) {
    const float2* S2 = (const float2*)(smem + SM_STAGE);
    #pragma unroll 4
    for (int i = tid; i < TILE_M * 64; i += NT) {
        frag_write(smem, i >> 6, i & 63, S2[i]);
    }
}

__device__ __forceinline__ void mma_mainloop(const char* smem,
                                             const uint4* __restrict__ bf,
                                             float c[8][4],
                                             int wid_m, int wid_n, int lane) {
    #pragma unroll
    for (int ks = 0; ks < 8; ks++) {
        u32 ah[4], al[4];
        *(uint4*)ah = *(const uint4*)(smem + SM_AHI + ((ks * 4 + wid_m) * 32 + lane) * 16);
        *(uint4*)al = *(const uint4*)(smem + SM_ALO + ((ks * 4 + wid_m) * 32 + lane) * 16);
        #pragma unroll
        for (int q = 0; q < 8; q++) {
            uint4 v = __ldg(&bf[(ks * 16 + wid_n * 8 + q) * 32 + lane]);
            u32 bh[2] = {v.x, v.y};
            u32 bl[2] = {v.z, v.w};
            mma_bf16(c[q], ah, bh);   // Ah*Bh
            mma_bf16(c[q], al, bh);   // Al*Bh
            mma_bf16(c[q], ah, bl);   // Ah*Bl
        }
    }
}

// ---------------------------------------------------------------------------
// gemm_pre: hpre = A @ W_pre + b_pre
// ---------------------------------------------------------------------------
__global__ void __launch_bounds__(NT, 2)
gemm_pre(const float* __restrict__ A, const float* __restrict__ bias,
         const uint4* __restrict__ bf, float* __restrict__ out, int nrows) {
    extern __shared__ char smem[];
    const int tid = threadIdx.x, wid = tid >> 5, lane = tid & 31;
    const int wid_m = wid >> 1, wid_n = wid & 1;
    const int base = blockIdx.x * TILE_M;

    float* bias_s = (float*)(smem + SM_B1);
    if (tid < 128) bias_s[tid] = bias[tid];
    stage_A_global(smem, A, base, nrows, tid);
    __syncthreads();

    float c[8][4];
    #pragma unroll
    for (int q = 0; q < 8; q++)
        #pragma unroll
        for (int r = 0; r < 4; r++) c[q][r] = 0.f;

    mma_mainloop(smem, bf, c, wid_m, wid_n, lane);

    const int g = lane >> 2, t = lane & 3;
    const int row0 = base + wid_m * 16 + g, row1 = row0 + 8;
    const bool ok0 = row0 < nrows, ok1 = row1 < nrows;
    float2* out2 = (float2*)out;
    #pragma unroll
    for (int q = 0; q < 8; q++) {
        int col = (wid_n * 8 + q) * 8 + t * 2;
        float2 b2 = *(const float2*)(bias_s + col);
        if (ok0) out2[(size_t)row0 * 64 + (col >> 1)] =
            make_float2(c[q][0] + b2.x, c[q][1] + b2.y);
        if (ok1) out2[(size_t)row1 * 64 + (col >> 1)] =
            make_float2(c[q][2] + b2.x, c[q][3] + b2.y);
    }
}

// ---------------------------------------------------------------------------
// gemm_mlp (fused gather):
//   agg = segment_sum(hpre[csr]) for this tile's 64 nodes (smem stage)
//   out = LayerNorm(hpre + relu(relu(agg@W1+b1)@W2+b2)) * gamma + beta
// ---------------------------------------------------------------------------
__global__ void __launch_bounds__(NT, 2)
gemm_mlp(const float* __restrict__ hpre,
         const float* __restrict__ b1v, const float* __restrict__ b2v,
         const uint4* __restrict__ bf1, const uint4* __restrict__ bf2,
         const float* __restrict__ gamma, const float* __restrict__ beta,
         float* __restrict__ out, int nrows) {
    extern __shared__ char smem[];
    const int tid = threadIdx.x, wid = tid >> 5, lane = tid & 31;
    const int wid_m = wid >> 1, wid_n = wid & 1;
    const int base = blockIdx.x * TILE_M;

    float* b1_s = (float*)(smem + SM_B1);
    float* b2_s = (float*)(smem + SM_B2);
    float* gm_s = (float*)(smem + SM_GAMMA);
    float* bt_s = (float*)(smem + SM_BETA);
    float2* red = (float2*)(smem + SM_RED);
    if (tid < 128) {
        b1_s[tid] = b1v[tid];
        b2_s[tid] = b2v[tid];
        gm_s[tid] = gamma[tid];
        bt_s[tid] = beta[tid];
    }

    // ---- Fused gather: warp w sums in-edges for nodes base+w*8..+8 ----
    {
        float4* st4 = (float4*)(smem + SM_STAGE);
        const float4* h4 = (const float4*)hpre;
        #pragma unroll 1
        for (int rr = 0; rr < 8; rr++) {
            int lrow = wid * 8 + rr;
            int node = base + lrow;
            float4 acc = make_float4(0.f, 0.f, 0.f, 0.f);
            if (node < nrows) {
                int e0 = g_off[node], e1 = g_off[node + 1];
                int e = e0;
                for (; e + 3 < e1; e += 4) {
                    int s0 = g_csr[e],     s1 = g_csr[e + 1];
                    int s2 = g_csr[e + 2], s3 = g_csr[e + 3];
                    float4 v0 = __ldg(&h4[(size_t)s0 * 32 + lane]);
                    float4 v1 = __ldg(&h4[(size_t)s1 * 32 + lane]);
                    float4 v2 = __ldg(&h4[(size_t)s2 * 32 + lane]);
                    float4 v3 = __ldg(&h4[(size_t)s3 * 32 + lane]);
                    acc.x += (v0.x + v1.x) + (v2.x + v3.x);
                    acc.y += (v0.y + v1.y) + (v2.y + v3.y);
                    acc.z += (v0.z + v1.z) + (v2.z + v3.z);
                    acc.w += (v0.w + v1.w) + (v2.w + v3.w);
                }
                for (; e < e1; e++) {
                    float4 v = __ldg(&h4[(size_t)g_csr[e] * 32 + lane]);
                    acc.x += v.x; acc.y += v.y; acc.z += v.z; acc.w += v.w;
                }
            }
            st4[lrow * 32 + lane] = acc;
        }
    }
    __syncthreads();
    stage_A_smem(smem, tid);
    __syncthreads();

    float c[8][4];
    #pragma unroll
    for (int q = 0; q < 8; q++)
        #pragma unroll
        for (int r = 0; r < 4; r++) c[q][r] = 0.f;

    // ---- GEMM 1: c = agg @ W1 ----
    mma_mainloop(smem, bf1, c, wid_m, wid_n, lane);

    __syncthreads();   // all warps done reading A-frags before overwrite

    // ---- Convert t1 = relu(c + b1) into A-frag smem (in-lane mapping) ----
    const int g = lane >> 2, t = lane & 3;
    {
        #pragma unroll
        for (int q2 = 0; q2 < 4; q2++) {
            int ks = wid_n * 4 + q2;
            u32 vh[4], vl[4];
            #pragma unroll
            for (int half = 0; half < 2; half++) {
                int q = 2 * q2 + half;
                int col = (wid_n * 8 + q) * 8 + t * 2;
                float2 b2 = *(const float2*)(b1_s + col);
                float v00 = fmaxf(c[q][0] + b2.x, 0.f);
                float v01 = fmaxf(c[q][1] + b2.y, 0.f);
                float v10 = fmaxf(c[q][2] + b2.x, 0.f);
                float v11 = fmaxf(c[q][3] + b2.y, 0.f);
                __nv_bfloat16 h00, l00, h01, l01, h10, l10, h11, l11;
                split2(v00, h00, l00); split2(v01, h01, l01);
                split2(v10, h10, l10); split2(v11, h11, l11);
                vh[half * 2 + 0] = pack_bf16x2(h00, h01);
                vh[half * 2 + 1] = pack_bf16x2(h10, h11);
                vl[half * 2 + 0] = pack_bf16x2(l00, l01);
                vl[half * 2 + 1] = pack_bf16x2(l10, l11);
            }
            int off = ((ks * 4 + wid_m) * 32 + lane) * 16;
            *(uint4*)(smem + SM_AHI + off) = *(uint4*)vh;
            *(uint4*)(smem + SM_ALO + off) = *(uint4*)vl;
        }
    }
    __syncthreads();

    #pragma unroll
    for (int q = 0; q < 8; q++)
        #pragma unroll
        for (int r = 0; r < 4; r++) c[q][r] = 0.f;

    // ---- GEMM 2: c = t1 @ W2 ----
    mma_mainloop(smem, bf2, c, wid_m, wid_n, lane);

    // ---- Epilogue: v = hpre + relu(c + b2); out = LN(v)*gamma + beta ----
    const int row0 = base + wid_m * 16 + g, row1 = row0 + 8;
    const int lr0 = wid_m * 16 + g, lr1 = lr0 + 8;
    const bool ok0 = row0 < nrows, ok1 = row1 < nrows;
    const float2* R2 = (const float2*)hpre;
    float s0 = 0.f, q0 = 0.f, s1 = 0.f, q1 = 0.f;
    #pragma unroll
    for (int q = 0; q < 8; q++) {
        int col = (wid_n * 8 + q) * 8 + t * 2;
        float2 b2 = *(const float2*)(b2_s + col);
        float2 r0 = ok0 ? R2[(size_t)row0 * 64 + (col >> 1)] : make_float2(0.f, 0.f);
        float2 r1 = ok1 ? R2[(size_t)row1 * 64 + (col >> 1)] : make_float2(0.f, 0.f);
        float v00 = fmaxf(c[q][0] + b2.x, 0.f) + r0.x;
        float v01 = fmaxf(c[q][1] + b2.y, 0.f) + r0.y;
        float v10 = fmaxf(c[q][2] + b2.x, 0.f) + r1.x;
        float v11 = fmaxf(c[q][3] + b2.y, 0.f) + r1.y;
        c[q][0] = v00; c[q][1] = v01; c[q][2] = v10; c[q][3] = v11;
        s0 += v00 + v01; q0 += v00 * v00 + v01 * v01;
        s1 += v10 + v11; q1 += v10 * v10 + v11 * v11;
    }
    #pragma unroll
    for (int off = 1; off <= 2; off <<= 1) {
        s0 += __shfl_xor_sync(0xFFFFFFFFu, s0, off);
        q0 += __shfl_xor_sync(0xFFFFFFFFu, q0, off);
        s1 += __shfl_xor_sync(0xFFFFFFFFu, s1, off);
        q1 += __shfl_xor_sync(0xFFFFFFFFu, q1, off);
    }
    if (t == 0) {
        red[lr0 * 2 + wid_n] = make_float2(s0, q0);
        red[lr1 * 2 + wid_n] = make_float2(s1, q1);
    }
    __syncthreads();
    {
        float2 a0 = red[lr0 * 2 + 0], a1 = red[lr0 * 2 + 1];
        float2 c0 = red[lr1 * 2 + 0], c1 = red[lr1 * 2 + 1];
        s0 = a0.x + a1.x; q0 = a0.y + a1.y;
        s1 = c0.x + c1.x; q1 = c0.y + c1.y;
    }
    float mean0 = s0 * (1.0f / D_DIM);
    float mean1 = s1 * (1.0f / D_DIM);
    float rstd0 = rsqrtf(q0 * (1.0f / D_DIM) - mean0 * mean0 + LN_EPS);
    float rstd1 = rsqrtf(q1 * (1.0f / D_DIM) - mean1 * mean1 + LN_EPS);
    float2* out2 = (float2*)out;
    #pragma unroll
    for (int q = 0; q < 8; q++) {
        int col = (wid_n * 8 + q) * 8 + t * 2;
        float2 g2 = *(const float2*)(gm_s + col);
        float2 t2 = *(const float2*)(bt_s + col);
        if (ok0) {
            float2 o;
            o.x = (c[q][0] - mean0) * rstd0 * g2.x + t2.x;
            o.y = (c[q][1] - mean0) * rstd0 * g2.y + t2.y;
            out2[(size_t)row0 * 64 + (col >> 1)] = o;
        }
        if (ok1) {
            float2 o;
            o.x = (c[q][2] - mean1) * rstd1 * g2.x + t2.x;
            o.y = (c[q][3] - mean1) * rstd1 * g2.y + t2.y;
            out2[(size_t)row1 * 64 + (col >> 1)] = o;
        }
    }
}

// ---------------------------------------------------------------------------
extern "C" void kernel_launch(void* const* d_in, const int* in_sizes, int n_in,
                              void* d_out, int out_size) {
    const float* h     = (const float*)d_in[0];
    const int*   src   = (const int*)  d_in[1];
    const int*   dst   = (const int*)  d_in[2];
    const float* W_pre = (const float*)d_in[3];
    const float* b_pre = (const float*)d_in[4];
    const float* W1    = (const float*)d_in[5];
    const float* b1    = (const float*)d_in[6];
    const float* W2    = (const float*)d_in[7];
    const float* b2    = (const float*)d_in[8];
    const float* gamma = (const float*)d_in[9];
    const float* beta  = (const float*)d_in[10];
    float* out = (float*)d_out;

    float* hpre;
    uint4* bf;
    cudaGetSymbolAddress((void**)&hpre, g_hpre);
    cudaGetSymbolAddress((void**)&bf,   g_bfrag);
    const uint4* bf_pre = bf;
    const uint4* bf_w1  = bf + 4096;
    const uint4* bf_w2  = bf + 8192;

    cudaFuncSetAttribute(gemm_pre, cudaFuncAttributeMaxDynamicSharedMemorySize, SMEM_TOTAL);
    cudaFuncSetAttribute(gemm_mlp, cudaFuncAttributeMaxDynamicSharedMemorySize, SMEM_TOTAL);

    const int blocks = (N_NODES + TILE_M - 1) / TILE_M;  // 782
    const int eblk   = (N_EDGES + 255) / 256;            // 2344

    // CSR build: hist -> offs -> fill (zero-state invariant maintained inline)
    hist_kernel<<<eblk, 256>>>(dst);
    offs_kernel<<<196, 256>>>();
    fill_kernel<<<eblk, 256>>>(src, dst);
    // Weights + pre-projection
    wprep_kernel<<<24, 256>>>(W_pre, W1, W2);
    gemm_pre<<<blocks, NT, SMEM_TOTAL>>>(h, b_pre, bf_pre, hpre, N_NODES);
    // Fused gather + MLP + residual + LayerNorm
    gemm_mlp<<<blocks, NT, SMEM_TOTAL>>>(hpre, b1, b2, bf_w1, bf_w2,
                                         gamma, beta, out, N_NODES);
    (void)in_sizes; (void)n_in; (void)out_size;
}

// round 11
// speedup vs baseline: 1.0482x; 1.0482x over previous
#include <cuda_runtime.h>
#include <cuda_bf16.h>
#include <math.h>
#include <stdint.h>

#define D_DIM 128
#define N_NODES 50000
#define N_EDGES 600000
#define LN_EPS 1e-5f
#define TILE_M 64
#define NT 256

typedef unsigned int u32;

// Scratch (allocation-free rule: __device__ globals)
__device__ float g_hpre[N_NODES * D_DIM];
__device__ float g_agg [N_NODES * D_DIM];
// Packed W fragments: [w][(ks*16+ni)*32+lane] = {hi0,hi1,lo0,lo1}
__device__ uint4 g_bfrag[3][4096];
// CSR build state. INVARIANT: g_cnt == 0 and g_bsum == 0 on entry to
// kernel_launch (static zero-init initially; offs/fill restore it each call).
__device__ int g_cnt[N_NODES];
__device__ int g_cur[N_NODES];
__device__ int g_off[N_NODES + 1];
__device__ int g_bsum[196];
__device__ int g_csr[N_EDGES];

// ---------------- smem layout (bytes) ----------------
#define SM_B1     0
#define SM_B2     512
#define SM_GAMMA  1024
#define SM_BETA   1536
#define SM_RED    2048          // 64 rows x 2 halves x float2 = 1KB
#define SM_AHI    4096          // A frags [ks8][mi4][lane32] x 16B = 16KB
#define SM_ALO    (SM_AHI + 16384)
#define SMEM_TOTAL (SM_ALO + 16384)   // 36864

__device__ __forceinline__ u32 pack_bf16x2(__nv_bfloat16 lo, __nv_bfloat16 hi) {
    __nv_bfloat162 v; v.x = lo; v.y = hi;
    return *(u32*)&v;
}
__device__ __forceinline__ void split2(float a, __nv_bfloat16& hi, __nv_bfloat16& lo) {
    hi = __float2bfloat16_rn(a);
    lo = __float2bfloat16_rn(a - __bfloat162float(hi));
}
__device__ __forceinline__ void mma_bf16(float* c, const u32* a, const u32* b) {
    asm volatile(
        "mma.sync.aligned.m16n8k16.row.col.f32.bf16.bf16.f32 "
        "{%0,%1,%2,%3}, {%4,%5,%6,%7}, {%8,%9}, {%0,%1,%2,%3};"
        : "+f"(c[0]), "+f"(c[1]), "+f"(c[2]), "+f"(c[3])
        : "r"(a[0]), "r"(a[1]), "r"(a[2]), "r"(a[3]), "r"(b[0]), "r"(b[1]));
}

// ---------------------------------------------------------------------------
// W prep: 3 weight matrices -> packed hi/lo B-fragment arrays. 96 CTAs.
// ---------------------------------------------------------------------------
__global__ void wprep_kernel(const float* __restrict__ W0,
                             const float* __restrict__ W1,
                             const float* __restrict__ W2) {
    const float* Ws[3] = {W0, W1, W2};
    int w = blockIdx.x >> 5, part = blockIdx.x & 31;   // 32 parts per matrix
    const float* W = Ws[w];
    uint4* bf = g_bfrag[w];
    for (int i = part * 256 + threadIdx.x; i < (part + 1) * 256; i += 256) {
        int j = i >> 7, n = i & 127;
        float w0 = W[(size_t)(2 * j)     * 128 + n];
        float w1 = W[(size_t)(2 * j + 1) * 128 + n];
        __nv_bfloat16 h0, l0, h1, l1;
        split2(w0, h0, l0);
        split2(w1, h1, l1);
        int ni = n >> 3, ks = j >> 3;
        int ln = ((n & 7) << 2) | (j & 3);
        int reg = (j >> 2) & 1;
        u32* slot = (u32*)&bf[(ks * 16 + ni) * 32 + ln];
        slot[reg]     = pack_bf16x2(h0, h1);
        slot[2 + reg] = pack_bf16x2(l0, l1);
    }
}

// ---------------------------------------------------------------------------
// CSR build (3 launches): hist -> offs -> fill
// ---------------------------------------------------------------------------
__global__ void hist_kernel(const int* __restrict__ dst) {
    int e = blockIdx.x * blockDim.x + threadIdx.x;
    if (e < N_EDGES) {
        int d = dst[e];
        atomicAdd(&g_cnt[d], 1);
        atomicAdd(&g_bsum[d >> 8], 1);   // per-256-node block sums
    }
}
__global__ void offs_kernel() {
    __shared__ int wsum[8];
    __shared__ int bpref_s;
    int b = blockIdx.x, t = threadIdx.x;
    int n = b * 256 + t;
    // block prefix: sum of g_bsum[0..b), one warp
    if (t < 32) {
        int s = 0;
        for (int i = t; i < b; i += 32) s += g_bsum[i];
        #pragma unroll
        for (int o = 16; o; o >>= 1) s += __shfl_xor_sync(0xFFFFFFFFu, s, o);
        if (t == 0) bpref_s = s;
    }
    int cnt = (n < N_NODES) ? g_cnt[n] : 0;
    if (n < N_NODES) g_cnt[n] = 0;        // restore invariant for next call
    // warp inclusive scan
    int x = cnt;
    #pragma unroll
    for (int o = 1; o < 32; o <<= 1) {
        int y = __shfl_up_sync(0xFFFFFFFFu, x, o);
        if ((t & 31) >= o) x += y;
    }
    if ((t & 31) == 31) wsum[t >> 5] = x;
    __syncthreads();
    if (t < 8) {
        int v = wsum[t];
        #pragma unroll
        for (int o = 1; o < 8; o <<= 1) {
            int y = __shfl_up_sync(0xFFu, v, o);
            if (t >= o) v += y;
        }
        wsum[t] = v;
    }
    __syncthreads();
    int wpref = (t >= 32) ? wsum[(t >> 5) - 1] : 0;
    int off = bpref_s + wpref + x - cnt;   // exclusive prefix
    if (n < N_NODES) { g_off[n] = off; g_cur[n] = off; }
    if (b == 195 && t == 255) g_off[N_NODES] = N_EDGES;
}
__global__ void fill_kernel(const int* __restrict__ src,
                            const int* __restrict__ dst) {
    int e = blockIdx.x * blockDim.x + threadIdx.x;
    if (e < 196) g_bsum[e] = 0;           // restore invariant
    if (e < N_EDGES) {
        int p = atomicAdd(&g_cur[dst[e]], 1);
        g_csr[p] = src[e];
    }
}

// ---------------------------------------------------------------------------
// Gather-sum: one warp per node, no atomics, 4-way edge unroll.
// ---------------------------------------------------------------------------
__global__ void gather_kernel(const float* __restrict__ hpre,
                              float* __restrict__ agg) {
    int gid  = blockIdx.x * blockDim.x + threadIdx.x;
    int node = gid >> 5;
    int lane = gid & 31;
    if (node >= N_NODES) return;
    int e0 = g_off[node], e1 = g_off[node + 1];
    float4 acc = make_float4(0.f, 0.f, 0.f, 0.f);
    const float4* h4 = (const float4*)hpre;
    int e = e0;
    for (; e + 3 < e1; e += 4) {
        int s0 = g_csr[e],     s1 = g_csr[e + 1];
        int s2 = g_csr[e + 2], s3 = g_csr[e + 3];
        float4 v0 = __ldg(&h4[(size_t)s0 * 32 + lane]);
        float4 v1 = __ldg(&h4[(size_t)s1 * 32 + lane]);
        float4 v2 = __ldg(&h4[(size_t)s2 * 32 + lane]);
        float4 v3 = __ldg(&h4[(size_t)s3 * 32 + lane]);
        acc.x += (v0.x + v1.x) + (v2.x + v3.x);
        acc.y += (v0.y + v1.y) + (v2.y + v3.y);
        acc.z += (v0.z + v1.z) + (v2.z + v3.z);
        acc.w += (v0.w + v1.w) + (v2.w + v3.w);
    }
    for (; e < e1; e++) {
        float4 v = __ldg(&h4[(size_t)g_csr[e] * 32 + lane]);
        acc.x += v.x; acc.y += v.y; acc.z += v.z; acc.w += v.w;
    }
    ((float4*)agg)[(size_t)node * 32 + lane] = acc;
}

// ---------------------------------------------------------------------------
// GEMM building blocks: TILE_M=64, 256 threads, 8 warps = (m 0..3, n 0..1)
// ---------------------------------------------------------------------------
__device__ __forceinline__ void stage_A(char* smem, const float* __restrict__ A,
                                        int base, int nrows, int tid) {
    const float2* A2 = (const float2*)A;
    #pragma unroll 4
    for (int i = tid; i < TILE_M * 64; i += NT) {
        int row = i >> 6, j = i & 63;
        float2 a = (base + row < nrows) ? A2[(size_t)(base + row) * 64 + j]
                                        : make_float2(0.f, 0.f);
        __nv_bfloat16 hx, lx, hy, ly;
        split2(a.x, hx, lx);
        split2(a.y, hy, ly);
        int mi = row >> 4, ks = j >> 3;
        int ln = ((row & 7) << 2) | (j & 3);
        int reg = (((j >> 2) & 1) << 1) | ((row >> 3) & 1);
        int off = ((ks * 4 + mi) * 32 + ln) * 16 + reg * 4;
        *(u32*)(smem + SM_AHI + off) = pack_bf16x2(hx, hy);
        *(u32*)(smem + SM_ALO + off) = pack_bf16x2(lx, ly);
    }
}

__device__ __forceinline__ void mma_mainloop(const char* smem,
                                             const uint4* __restrict__ bf,
                                             float c[8][4],
                                             int wid_m, int wid_n, int lane) {
    #pragma unroll
    for (int ks = 0; ks < 8; ks++) {
        u32 ah[4], al[4];
        *(uint4*)ah = *(const uint4*)(smem + SM_AHI + ((ks * 4 + wid_m) * 32 + lane) * 16);
        *(uint4*)al = *(const uint4*)(smem + SM_ALO + ((ks * 4 + wid_m) * 32 + lane) * 16);
        #pragma unroll
        for (int q = 0; q < 8; q++) {
            uint4 v = __ldg(&bf[(ks * 16 + wid_n * 8 + q) * 32 + lane]);
            u32 bh[2] = {v.x, v.y};
            u32 bl[2] = {v.z, v.w};
            mma_bf16(c[q], ah, bh);   // Ah*Bh
            mma_bf16(c[q], al, bh);   // Al*Bh
            mma_bf16(c[q], ah, bl);   // Ah*Bl
        }
    }
}

// ---------------------------------------------------------------------------
// gemm_pre: hpre = A @ W_pre + b_pre
// ---------------------------------------------------------------------------
__global__ void __launch_bounds__(NT, 2)
gemm_pre(const float* __restrict__ A, const float* __restrict__ bias,
         const uint4* __restrict__ bf, float* __restrict__ out, int nrows) {
    extern __shared__ char smem[];
    const int tid = threadIdx.x, wid = tid >> 5, lane = tid & 31;
    const int wid_m = wid >> 1, wid_n = wid & 1;
    const int base = blockIdx.x * TILE_M;

    float* bias_s = (float*)(smem + SM_B1);
    if (tid < 128) bias_s[tid] = bias[tid];
    stage_A(smem, A, base, nrows, tid);
    __syncthreads();

    float c[8][4];
    #pragma unroll
    for (int q = 0; q < 8; q++)
        #pragma unroll
        for (int r = 0; r < 4; r++) c[q][r] = 0.f;

    mma_mainloop(smem, bf, c, wid_m, wid_n, lane);

    const int g = lane >> 2, t = lane & 3;
    const int row0 = base + wid_m * 16 + g, row1 = row0 + 8;
    const bool ok0 = row0 < nrows, ok1 = row1 < nrows;
    float2* out2 = (float2*)out;
    #pragma unroll
    for (int q = 0; q < 8; q++) {
        int col = (wid_n * 8 + q) * 8 + t * 2;
        float2 b2 = *(const float2*)(bias_s + col);
        if (ok0) out2[(size_t)row0 * 64 + (col >> 1)] =
            make_float2(c[q][0] + b2.x, c[q][1] + b2.y);
        if (ok1) out2[(size_t)row1 * 64 + (col >> 1)] =
            make_float2(c[q][2] + b2.x, c[q][3] + b2.y);
    }
}

// ---------------------------------------------------------------------------
// gemm_mlp: out = LayerNorm(resid + relu(relu(A@W1+b1)@W2+b2)) * gamma + beta
// ---------------------------------------------------------------------------
__global__ void __launch_bounds__(NT, 2)
gemm_mlp(const float* __restrict__ A,
         const float* __restrict__ b1v, const float* __restrict__ b2v,
         const uint4* __restrict__ bf1, const uint4* __restrict__ bf2,
         const float* __restrict__ resid,
         const float* __restrict__ gamma, const float* __restrict__ beta,
         float* __restrict__ out, int nrows) {
    extern __shared__ char smem[];
    const int tid = threadIdx.x, wid = tid >> 5, lane = tid & 31;
    const int wid_m = wid >> 1, wid_n = wid & 1;
    const int base = blockIdx.x * TILE_M;

    float* b1_s = (float*)(smem + SM_B1);
    float* b2_s = (float*)(smem + SM_B2);
    float* gm_s = (float*)(smem + SM_GAMMA);
    float* bt_s = (float*)(smem + SM_BETA);
    float2* red = (float2*)(smem + SM_RED);
    if (tid < 128) {
        b1_s[tid] = b1v[tid];
        b2_s[tid] = b2v[tid];
        gm_s[tid] = gamma[tid];
        bt_s[tid] = beta[tid];
    }
    stage_A(smem, A, base, nrows, tid);
    __syncthreads();

    float c[8][4];
    #pragma unroll
    for (int q = 0; q < 8; q++)
        #pragma unroll
        for (int r = 0; r < 4; r++) c[q][r] = 0.f;

    // ---- GEMM 1: c = A @ W1 ----
    mma_mainloop(smem, bf1, c, wid_m, wid_n, lane);

    __syncthreads();   // all warps done reading A-frags before overwrite

    // ---- Convert t1 = relu(c + b1) into A-frag smem (in-lane mapping) ----
    const int g = lane >> 2, t = lane & 3;
    {
        #pragma unroll
        for (int q2 = 0; q2 < 4; q2++) {
            int ks = wid_n * 4 + q2;
            u32 vh[4], vl[4];
            #pragma unroll
            for (int half = 0; half < 2; half++) {
                int q = 2 * q2 + half;
                int col = (wid_n * 8 + q) * 8 + t * 2;
                float2 b2 = *(const float2*)(b1_s + col);
                float v00 = fmaxf(c[q][0] + b2.x, 0.f);
                float v01 = fmaxf(c[q][1] + b2.y, 0.f);
                float v10 = fmaxf(c[q][2] + b2.x, 0.f);
                float v11 = fmaxf(c[q][3] + b2.y, 0.f);
                __nv_bfloat16 h00, l00, h01, l01, h10, l10, h11, l11;
                split2(v00, h00, l00); split2(v01, h01, l01);
                split2(v10, h10, l10); split2(v11, h11, l11);
                vh[half * 2 + 0] = pack_bf16x2(h00, h01);
                vh[half * 2 + 1] = pack_bf16x2(h10, h11);
                vl[half * 2 + 0] = pack_bf16x2(l00, l01);
                vl[half * 2 + 1] = pack_bf16x2(l10, l11);
            }
            int off = ((ks * 4 + wid_m) * 32 + lane) * 16;
            *(uint4*)(smem + SM_AHI + off) = *(uint4*)vh;
            *(uint4*)(smem + SM_ALO + off) = *(uint4*)vl;
        }
    }
    __syncthreads();

    #pragma unroll
    for (int q = 0; q < 8; q++)
        #pragma unroll
        for (int r = 0; r < 4; r++) c[q][r] = 0.f;

    // ---- GEMM 2: c = t1 @ W2 ----
    mma_mainloop(smem, bf2, c, wid_m, wid_n, lane);

    // ---- Epilogue: v = resid + relu(c + b2); out = LN(v)*gamma + beta ----
    const int row0 = base + wid_m * 16 + g, row1 = row0 + 8;
    const int lr0 = wid_m * 16 + g, lr1 = lr0 + 8;
    const bool ok0 = row0 < nrows, ok1 = row1 < nrows;
    const float2* R2 = (const float2*)resid;
    float s0 = 0.f, q0 = 0.f, s1 = 0.f, q1 = 0.f;
    #pragma unroll
    for (int q = 0; q < 8; q++) {
        int col = (wid_n * 8 + q) * 8 + t * 2;
        float2 b2 = *(const float2*)(b2_s + col);
        float2 r0 = ok0 ? R2[(size_t)row0 * 64 + (col >> 1)] : make_float2(0.f, 0.f);
        float2 r1 = ok1 ? R2[(size_t)row1 * 64 + (col >> 1)] : make_float2(0.f, 0.f);
        float v00 = fmaxf(c[q][0] + b2.x, 0.f) + r0.x;
        float v01 = fmaxf(c[q][1] + b2.y, 0.f) + r0.y;
        float v10 = fmaxf(c[q][2] + b2.x, 0.f) + r1.x;
        float v11 = fmaxf(c[q][3] + b2.y, 0.f) + r1.y;
        c[q][0] = v00; c[q][1] = v01; c[q][2] = v10; c[q][3] = v11;
        s0 += v00 + v01; q0 += v00 * v00 + v01 * v01;
        s1 += v10 + v11; q1 += v10 * v10 + v11 * v11;
    }
    #pragma unroll
    for (int off = 1; off <= 2; off <<= 1) {
        s0 += __shfl_xor_sync(0xFFFFFFFFu, s0, off);
        q0 += __shfl_xor_sync(0xFFFFFFFFu, q0, off);
        s1 += __shfl_xor_sync(0xFFFFFFFFu, s1, off);
        q1 += __shfl_xor_sync(0xFFFFFFFFu, q1, off);
    }
    if (t == 0) {
        red[lr0 * 2 + wid_n] = make_float2(s0, q0);
        red[lr1 * 2 + wid_n] = make_float2(s1, q1);
    }
    __syncthreads();
    {
        float2 a0 = red[lr0 * 2 + 0], a1 = red[lr0 * 2 + 1];
        float2 c0 = red[lr1 * 2 + 0], c1 = red[lr1 * 2 + 1];
        s0 = a0.x + a1.x; q0 = a0.y + a1.y;
        s1 = c0.x + c1.x; q1 = c0.y + c1.y;
    }
    float mean0 = s0 * (1.0f / D_DIM);
    float mean1 = s1 * (1.0f / D_DIM);
    float rstd0 = rsqrtf(q0 * (1.0f / D_DIM) - mean0 * mean0 + LN_EPS);
    float rstd1 = rsqrtf(q1 * (1.0f / D_DIM) - mean1 * mean1 + LN_EPS);
    float2* out2 = (float2*)out;
    #pragma unroll
    for (int q = 0; q < 8; q++) {
        int col = (wid_n * 8 + q) * 8 + t * 2;
        float2 g2 = *(const float2*)(gm_s + col);
        float2 t2 = *(const float2*)(bt_s + col);
        if (ok0) {
            float2 o;
            o.x = (c[q][0] - mean0) * rstd0 * g2.x + t2.x;
            o.y = (c[q][1] - mean0) * rstd0 * g2.y + t2.y;
            out2[(size_t)row0 * 64 + (col >> 1)] = o;
        }
        if (ok1) {
            float2 o;
            o.x = (c[q][2] - mean1) * rstd1 * g2.x + t2.x;
            o.y = (c[q][3] - mean1) * rstd1 * g2.y + t2.y;
            out2[(size_t)row1 * 64 + (col >> 1)] = o;
        }
    }
}

// ---------------------------------------------------------------------------
extern "C" void kernel_launch(void* const* d_in, const int* in_sizes, int n_in,
                              void* d_out, int out_size) {
    const float* h     = (const float*)d_in[0];
    const int*   src   = (const int*)  d_in[1];
    const int*   dst   = (const int*)  d_in[2];
    const float* W_pre = (const float*)d_in[3];
    const float* b_pre = (const float*)d_in[4];
    const float* W1    = (const float*)d_in[5];
    const float* b1    = (const float*)d_in[6];
    const float* W2    = (const float*)d_in[7];
    const float* b2    = (const float*)d_in[8];
    const float* gamma = (const float*)d_in[9];
    const float* beta  = (const float*)d_in[10];
    float* out = (float*)d_out;

    float *hpre, *agg;
    uint4* bf;
    cudaGetSymbolAddress((void**)&hpre, g_hpre);
    cudaGetSymbolAddress((void**)&agg,  g_agg);
    cudaGetSymbolAddress((void**)&bf,   g_bfrag);
    const uint4* bf_pre = bf;
    const uint4* bf_w1  = bf + 4096;
    const uint4* bf_w2  = bf + 8192;

    cudaFuncSetAttribute(gemm_pre, cudaFuncAttributeMaxDynamicSharedMemorySize, SMEM_TOTAL);
    cudaFuncSetAttribute(gemm_mlp, cudaFuncAttributeMaxDynamicSharedMemorySize, SMEM_TOTAL);

    const int blocks = (N_NODES + TILE_M - 1) / TILE_M;  // 782
    const int eblk   = (N_EDGES + 255) / 256;            // 2344

    // CSR build: hist -> offs -> fill (zero-state invariant maintained inline)
    hist_kernel<<<eblk, 256>>>(dst);
    offs_kernel<<<196, 256>>>();
    fill_kernel<<<eblk, 256>>>(src, dst);
    // Weights + pre-projection
    wprep_kernel<<<96, 256>>>(W_pre, W1, W2);
    gemm_pre<<<blocks, NT, SMEM_TOTAL>>>(h, b_pre, bf_pre, hpre, N_NODES);
    // agg[n] = sum of hpre[src] over in-edges (no atomics, warp per node)
    gather_kernel<<<(N_NODES * 32 + 255) / 256, 256>>>(hpre, agg);
    // Fused MLP + residual + LayerNorm
    gemm_mlp<<<blocks, NT, SMEM_TOTAL>>>(agg, b1, b2, bf_w1, bf_w2,
                                         hpre, gamma, beta, out, N_NODES);
    (void)in_sizes; (void)n_in; (void)out_size;
}

// round 12
// speedup vs baseline: 1.7402x; 1.6602x over previous
#include <cuda_runtime.h>
#include <cuda_bf16.h>
#include <math.h>
#include <stdint.h>

#define D_DIM 128
#define N_NODES 50000
#define N_EDGES 600000
#define LN_EPS 1e-5f
#define TILE_M 64
#define NT 256

typedef unsigned int u32;

// Scratch (allocation-free rule: __device__ globals)
__device__ float g_hpre[N_NODES * D_DIM];
__device__ float g_agg [N_NODES * D_DIM];
// Packed W fragments: [w][(ks*16+ni)*32+lane] = {hi0,hi1,lo0,lo1}
__device__ uint4 g_bfrag[3][4096];
// CSR build state. INVARIANT: g_cnt == 0 on entry to kernel_launch
// (static zero-init initially; offs_kernel restores it every call).
__device__ int g_cnt[N_NODES];
__device__ int g_cur[N_NODES];
__device__ int g_off[N_NODES + 1];
__device__ int g_bsum[196];
__device__ int g_csr[N_EDGES];

// ---------------- smem layout (bytes) ----------------
#define SM_B1     0
#define SM_B2     512
#define SM_GAMMA  1024
#define SM_BETA   1536
#define SM_RED    2048          // 64 rows x 2 halves x float2 = 1KB
#define SM_AHI    4096          // A frags [ks8][mi4][lane32] x 16B = 16KB
#define SM_ALO    (SM_AHI + 16384)
#define SMEM_TOTAL (SM_ALO + 16384)   // 36864

__device__ __forceinline__ u32 pack_bf16x2(__nv_bfloat16 lo, __nv_bfloat16 hi) {
    __nv_bfloat162 v; v.x = lo; v.y = hi;
    return *(u32*)&v;
}
__device__ __forceinline__ void split2(float a, __nv_bfloat16& hi, __nv_bfloat16& lo) {
    hi = __float2bfloat16_rn(a);
    lo = __float2bfloat16_rn(a - __bfloat162float(hi));
}
__device__ __forceinline__ void mma_bf16(float* c, const u32* a, const u32* b) {
    asm volatile(
        "mma.sync.aligned.m16n8k16.row.col.f32.bf16.bf16.f32 "
        "{%0,%1,%2,%3}, {%4,%5,%6,%7}, {%8,%9}, {%0,%1,%2,%3};"
        : "+f"(c[0]), "+f"(c[1]), "+f"(c[2]), "+f"(c[3])
        : "r"(a[0]), "r"(a[1]), "r"(a[2]), "r"(a[3]), "r"(b[0]), "r"(b[1]));
}

// ---------------------------------------------------------------------------
// W prep: 3 weight matrices -> packed hi/lo B-fragment arrays. 96 CTAs.
// ---------------------------------------------------------------------------
__global__ void wprep_kernel(const float* __restrict__ W0,
                             const float* __restrict__ W1,
                             const float* __restrict__ W2) {
    const float* Ws[3] = {W0, W1, W2};
    int w = blockIdx.x >> 5, part = blockIdx.x & 31;
    const float* W = Ws[w];
    uint4* bf = g_bfrag[w];
    for (int i = part * 256 + threadIdx.x; i < (part + 1) * 256; i += 256) {
        int j = i >> 7, n = i & 127;
        float w0 = W[(size_t)(2 * j)     * 128 + n];
        float w1 = W[(size_t)(2 * j + 1) * 128 + n];
        __nv_bfloat16 h0, l0, h1, l1;
        split2(w0, h0, l0);
        split2(w1, h1, l1);
        int ni = n >> 3, ks = j >> 3;
        int ln = ((n & 7) << 2) | (j & 3);
        int reg = (j >> 2) & 1;
        u32* slot = (u32*)&bf[(ks * 16 + ni) * 32 + ln];
        slot[reg]     = pack_bf16x2(h0, h1);
        slot[2 + reg] = pack_bf16x2(l0, l1);
    }
}

// ---------------------------------------------------------------------------
// CSR build (4 launches): hist -> bsum -> offs -> fill.
// NOTE: NO low-cardinality atomics (600k atomics on 196 addresses serialize
// at the LTS atomic ALU and cost ~75us — measured in rounds 10/11).
// ---------------------------------------------------------------------------
__global__ void hist_kernel(const int* __restrict__ dst) {
    int e = blockIdx.x * blockDim.x + threadIdx.x;
    if (e < N_EDGES) atomicAdd(&g_cnt[dst[e]], 1);   // 50k addresses: OK
}
__global__ void bsum_kernel() {   // block b sums g_cnt[b*256 .. b*256+256)
    __shared__ int s[256];
    int n = blockIdx.x * 256 + threadIdx.x;
    s[threadIdx.x] = (n < N_NODES) ? g_cnt[n] : 0;
    __syncthreads();
    #pragma unroll
    for (int w = 128; w > 0; w >>= 1) {
        if (threadIdx.x < w) s[threadIdx.x] += s[threadIdx.x + w];
        __syncthreads();
    }
    if (threadIdx.x == 0) g_bsum[blockIdx.x] = s[0];
}
__global__ void offs_kernel() {
    __shared__ int wsum[8];
    __shared__ int bpref_s;
    int b = blockIdx.x, t = threadIdx.x;
    int n = b * 256 + t;
    // block prefix: sum of g_bsum[0..b), one warp
    if (t < 32) {
        int s = 0;
        for (int i = t; i < b; i += 32) s += g_bsum[i];
        #pragma unroll
        for (int o = 16; o; o >>= 1) s += __shfl_xor_sync(0xFFFFFFFFu, s, o);
        if (t == 0) bpref_s = s;
    }
    int cnt = (n < N_NODES) ? g_cnt[n] : 0;
    if (n < N_NODES) g_cnt[n] = 0;        // restore invariant for next call
    // warp inclusive scan
    int x = cnt;
    #pragma unroll
    for (int o = 1; o < 32; o <<= 1) {
        int y = __shfl_up_sync(0xFFFFFFFFu, x, o);
        if ((t & 31) >= o) x += y;
    }
    if ((t & 31) == 31) wsum[t >> 5] = x;
    __syncthreads();
    if (t < 8) {
        int v = wsum[t];
        #pragma unroll
        for (int o = 1; o < 8; o <<= 1) {
            int y = __shfl_up_sync(0xFFu, v, o);
            if (t >= o) v += y;
        }
        wsum[t] = v;
    }
    __syncthreads();
    int wpref = (t >= 32) ? wsum[(t >> 5) - 1] : 0;
    int off = bpref_s + wpref + x - cnt;   // exclusive prefix
    if (n < N_NODES) { g_off[n] = off; g_cur[n] = off; }
    if (b == 195 && t == 255) g_off[N_NODES] = N_EDGES;
}
__global__ void fill_kernel(const int* __restrict__ src,
                            const int* __restrict__ dst) {
    int e = blockIdx.x * blockDim.x + threadIdx.x;
    if (e < N_EDGES) {
        int p = atomicAdd(&g_cur[dst[e]], 1);
        g_csr[p] = src[e];
    }
}

// ---------------------------------------------------------------------------
// Gather-sum: one warp per node, no atomics, 4-way edge unroll.
// ---------------------------------------------------------------------------
__global__ void gather_kernel(const float* __restrict__ hpre,
                              float* __restrict__ agg) {
    int gid  = blockIdx.x * blockDim.x + threadIdx.x;
    int node = gid >> 5;
    int lane = gid & 31;
    if (node >= N_NODES) return;
    int e0 = g_off[node], e1 = g_off[node + 1];
    float4 acc = make_float4(0.f, 0.f, 0.f, 0.f);
    const float4* h4 = (const float4*)hpre;
    int e = e0;
    for (; e + 3 < e1; e += 4) {
        int s0 = g_csr[e],     s1 = g_csr[e + 1];
        int s2 = g_csr[e + 2], s3 = g_csr[e + 3];
        float4 v0 = __ldg(&h4[(size_t)s0 * 32 + lane]);
        float4 v1 = __ldg(&h4[(size_t)s1 * 32 + lane]);
        float4 v2 = __ldg(&h4[(size_t)s2 * 32 + lane]);
        float4 v3 = __ldg(&h4[(size_t)s3 * 32 + lane]);
        acc.x += (v0.x + v1.x) + (v2.x + v3.x);
        acc.y += (v0.y + v1.y) + (v2.y + v3.y);
        acc.z += (v0.z + v1.z) + (v2.z + v3.z);
        acc.w += (v0.w + v1.w) + (v2.w + v3.w);
    }
    for (; e < e1; e++) {
        float4 v = __ldg(&h4[(size_t)g_csr[e] * 32 + lane]);
        acc.x += v.x; acc.y += v.y; acc.z += v.z; acc.w += v.w;
    }
    ((float4*)agg)[(size_t)node * 32 + lane] = acc;
}

// ---------------------------------------------------------------------------
// GEMM building blocks: TILE_M=64, 256 threads, 8 warps = (m 0..3, n 0..1)
// ---------------------------------------------------------------------------
__device__ __forceinline__ void stage_A(char* smem, const float* __restrict__ A,
                                        int base, int nrows, int tid) {
    const float2* A2 = (const float2*)A;
    #pragma unroll 4
    for (int i = tid; i < TILE_M * 64; i += NT) {
        int row = i >> 6, j = i & 63;
        float2 a = (base + row < nrows) ? A2[(size_t)(base + row) * 64 + j]
                                        : make_float2(0.f, 0.f);
        __nv_bfloat16 hx, lx, hy, ly;
        split2(a.x, hx, lx);
        split2(a.y, hy, ly);
        int mi = row >> 4, ks = j >> 3;
        int ln = ((row & 7) << 2) | (j & 3);
        int reg = (((j >> 2) & 1) << 1) | ((row >> 3) & 1);
        int off = ((ks * 4 + mi) * 32 + ln) * 16 + reg * 4;
        *(u32*)(smem + SM_AHI + off) = pack_bf16x2(hx, hy);
        *(u32*)(smem + SM_ALO + off) = pack_bf16x2(lx, ly);
    }
}

__device__ __forceinline__ void mma_mainloop(const char* smem,
                                             const uint4* __restrict__ bf,
                                             float c[8][4],
                                             int wid_m, int wid_n, int lane) {
    #pragma unroll
    for (int ks = 0; ks < 8; ks++) {
        u32 ah[4], al[4];
        *(uint4*)ah = *(const uint4*)(smem + SM_AHI + ((ks * 4 + wid_m) * 32 + lane) * 16);
        *(uint4*)al = *(const uint4*)(smem + SM_ALO + ((ks * 4 + wid_m) * 32 + lane) * 16);
        #pragma unroll
        for (int q = 0; q < 8; q++) {
            uint4 v = __ldg(&bf[(ks * 16 + wid_n * 8 + q) * 32 + lane]);
            u32 bh[2] = {v.x, v.y};
            u32 bl[2] = {v.z, v.w};
            mma_bf16(c[q], ah, bh);   // Ah*Bh
            mma_bf16(c[q], al, bh);   // Al*Bh
            mma_bf16(c[q], ah, bl);   // Ah*Bl
        }
    }
}

// ---------------------------------------------------------------------------
// gemm_pre: hpre = A @ W_pre + b_pre
// ---------------------------------------------------------------------------
__global__ void __launch_bounds__(NT, 2)
gemm_pre(const float* __restrict__ A, const float* __restrict__ bias,
         const uint4* __restrict__ bf, float* __restrict__ out, int nrows) {
    extern __shared__ char smem[];
    const int tid = threadIdx.x, wid = tid >> 5, lane = tid & 31;
    const int wid_m = wid >> 1, wid_n = wid & 1;
    const int base = blockIdx.x * TILE_M;

    float* bias_s = (float*)(smem + SM_B1);
    if (tid < 128) bias_s[tid] = bias[tid];
    stage_A(smem, A, base, nrows, tid);
    __syncthreads();

    float c[8][4];
    #pragma unroll
    for (int q = 0; q < 8; q++)
        #pragma unroll
        for (int r = 0; r < 4; r++) c[q][r] = 0.f;

    mma_mainloop(smem, bf, c, wid_m, wid_n, lane);

    const int g = lane >> 2, t = lane & 3;
    const int row0 = base + wid_m * 16 + g, row1 = row0 + 8;
    const bool ok0 = row0 < nrows, ok1 = row1 < nrows;
    float2* out2 = (float2*)out;
    #pragma unroll
    for (int q = 0; q < 8; q++) {
        int col = (wid_n * 8 + q) * 8 + t * 2;
        float2 b2 = *(const float2*)(bias_s + col);
        if (ok0) out2[(size_t)row0 * 64 + (col >> 1)] =
            make_float2(c[q][0] + b2.x, c[q][1] + b2.y);
        if (ok1) out2[(size_t)row1 * 64 + (col >> 1)] =
            make_float2(c[q][2] + b2.x, c[q][3] + b2.y);
    }
}

// ---------------------------------------------------------------------------
// gemm_mlp: out = LayerNorm(resid + relu(relu(A@W1+b1)@W2+b2)) * gamma + beta
// ---------------------------------------------------------------------------
__global__ void __launch_bounds__(NT, 2)
gemm_mlp(const float* __restrict__ A,
         const float* __restrict__ b1v, const float* __restrict__ b2v,
         const uint4* __restrict__ bf1, const uint4* __restrict__ bf2,
         const float* __restrict__ resid,
         const float* __restrict__ gamma, const float* __restrict__ beta,
         float* __restrict__ out, int nrows) {
    extern __shared__ char smem[];
    const int tid = threadIdx.x, wid = tid >> 5, lane = tid & 31;
    const int wid_m = wid >> 1, wid_n = wid & 1;
    const int base = blockIdx.x * TILE_M;

    float* b1_s = (float*)(smem + SM_B1);
    float* b2_s = (float*)(smem + SM_B2);
    float* gm_s = (float*)(smem + SM_GAMMA);
    float* bt_s = (float*)(smem + SM_BETA);
    float2* red = (float2*)(smem + SM_RED);
    if (tid < 128) {
        b1_s[tid] = b1v[tid];
        b2_s[tid] = b2v[tid];
        gm_s[tid] = gamma[tid];
        bt_s[tid] = beta[tid];
    }
    stage_A(smem, A, base, nrows, tid);
    __syncthreads();

    float c[8][4];
    #pragma unroll
    for (int q = 0; q < 8; q++)
        #pragma unroll
        for (int r = 0; r < 4; r++) c[q][r] = 0.f;

    // ---- GEMM 1: c = A @ W1 ----
    mma_mainloop(smem, bf1, c, wid_m, wid_n, lane);

    __syncthreads();   // all warps done reading A-frags before overwrite

    // ---- Convert t1 = relu(c + b1) into A-frag smem (in-lane mapping) ----
    const int g = lane >> 2, t = lane & 3;
    {
        #pragma unroll
        for (int q2 = 0; q2 < 4; q2++) {
            int ks = wid_n * 4 + q2;
            u32 vh[4], vl[4];
            #pragma unroll
            for (int half = 0; half < 2; half++) {
                int q = 2 * q2 + half;
                int col = (wid_n * 8 + q) * 8 + t * 2;
                float2 b2 = *(const float2*)(b1_s + col);
                float v00 = fmaxf(c[q][0] + b2.x, 0.f);
                float v01 = fmaxf(c[q][1] + b2.y, 0.f);
                float v10 = fmaxf(c[q][2] + b2.x, 0.f);
                float v11 = fmaxf(c[q][3] + b2.y, 0.f);
                __nv_bfloat16 h00, l00, h01, l01, h10, l10, h11, l11;
                split2(v00, h00, l00); split2(v01, h01, l01);
                split2(v10, h10, l10); split2(v11, h11, l11);
                vh[half * 2 + 0] = pack_bf16x2(h00, h01);
                vh[half * 2 + 1] = pack_bf16x2(h10, h11);
                vl[half * 2 + 0] = pack_bf16x2(l00, l01);
                vl[half * 2 + 1] = pack_bf16x2(l10, l11);
            }
            int off = ((ks * 4 + wid_m) * 32 + lane) * 16;
            *(uint4*)(smem + SM_AHI + off) = *(uint4*)vh;
            *(uint4*)(smem + SM_ALO + off) = *(uint4*)vl;
        }
    }
    __syncthreads();

    #pragma unroll
    for (int q = 0; q < 8; q++)
        #pragma unroll
        for (int r = 0; r < 4; r++) c[q][r] = 0.f;

    // ---- GEMM 2: c = t1 @ W2 ----
    mma_mainloop(smem, bf2, c, wid_m, wid_n, lane);

    // ---- Epilogue: v = resid + relu(c + b2); out = LN(v)*gamma + beta ----
    const int row0 = base + wid_m * 16 + g, row1 = row0 + 8;
    const int lr0 = wid_m * 16 + g, lr1 = lr0 + 8;
    const bool ok0 = row0 < nrows, ok1 = row1 < nrows;
    const float2* R2 = (const float2*)resid;
    float s0 = 0.f, q0 = 0.f, s1 = 0.f, q1 = 0.f;
    #pragma unroll
    for (int q = 0; q < 8; q++) {
        int col = (wid_n * 8 + q) * 8 + t * 2;
        float2 b2 = *(const float2*)(b2_s + col);
        float2 r0 = ok0 ? R2[(size_t)row0 * 64 + (col >> 1)] : make_float2(0.f, 0.f);
        float2 r1 = ok1 ? R2[(size_t)row1 * 64 + (col >> 1)] : make_float2(0.f, 0.f);
        float v00 = fmaxf(c[q][0] + b2.x, 0.f) + r0.x;
        float v01 = fmaxf(c[q][1] + b2.y, 0.f) + r0.y;
        float v10 = fmaxf(c[q][2] + b2.x, 0.f) + r1.x;
        float v11 = fmaxf(c[q][3] + b2.y, 0.f) + r1.y;
        c[q][0] = v00; c[q][1] = v01; c[q][2] = v10; c[q][3] = v11;
        s0 += v00 + v01; q0 += v00 * v00 + v01 * v01;
        s1 += v10 + v11; q1 += v10 * v10 + v11 * v11;
    }
    #pragma unroll
    for (int off = 1; off <= 2; off <<= 1) {
        s0 += __shfl_xor_sync(0xFFFFFFFFu, s0, off);
        q0 += __shfl_xor_sync(0xFFFFFFFFu, q0, off);
        s1 += __shfl_xor_sync(0xFFFFFFFFu, s1, off);
        q1 += __shfl_xor_sync(0xFFFFFFFFu, q1, off);
    }
    if (t == 0) {
        red[lr0 * 2 + wid_n] = make_float2(s0, q0);
        red[lr1 * 2 + wid_n] = make_float2(s1, q1);
    }
    __syncthreads();
    {
        float2 a0 = red[lr0 * 2 + 0], a1 = red[lr0 * 2 + 1];
        float2 c0 = red[lr1 * 2 + 0], c1 = red[lr1 * 2 + 1];
        s0 = a0.x + a1.x; q0 = a0.y + a1.y;
        s1 = c0.x + c1.x; q1 = c0.y + c1.y;
    }
    float mean0 = s0 * (1.0f / D_DIM);
    float mean1 = s1 * (1.0f / D_DIM);
    float rstd0 = rsqrtf(q0 * (1.0f / D_DIM) - mean0 * mean0 + LN_EPS);
    float rstd1 = rsqrtf(q1 * (1.0f / D_DIM) - mean1 * mean1 + LN_EPS);
    float2* out2 = (float2*)out;
    #pragma unroll
    for (int q = 0; q < 8; q++) {
        int col = (wid_n * 8 + q) * 8 + t * 2;
        float2 g2 = *(const float2*)(gm_s + col);
        float2 t2 = *(const float2*)(bt_s + col);
        if (ok0) {
            float2 o;
            o.x = (c[q][0] - mean0) * rstd0 * g2.x + t2.x;
            o.y = (c[q][1] - mean0) * rstd0 * g2.y + t2.y;
            out2[(size_t)row0 * 64 + (col >> 1)] = o;
        }
        if (ok1) {
            float2 o;
            o.x = (c[q][2] - mean1) * rstd1 * g2.x + t2.x;
            o.y = (c[q][3] - mean1) * rstd1 * g2.y + t2.y;
            out2[(size_t)row1 * 64 + (col >> 1)] = o;
        }
    }
}

// ---------------------------------------------------------------------------
extern "C" void kernel_launch(void* const* d_in, const int* in_sizes, int n_in,
                              void* d_out, int out_size) {
    const float* h     = (const float*)d_in[0];
    const int*   src   = (const int*)  d_in[1];
    const int*   dst   = (const int*)  d_in[2];
    const float* W_pre = (const float*)d_in[3];
    const float* b_pre = (const float*)d_in[4];
    const float* W1    = (const float*)d_in[5];
    const float* b1    = (const float*)d_in[6];
    const float* W2    = (const float*)d_in[7];
    const float* b2    = (const float*)d_in[8];
    const float* gamma = (const float*)d_in[9];
    const float* beta  = (const float*)d_in[10];
    float* out = (float*)d_out;

    float *hpre, *agg;
    uint4* bf;
    cudaGetSymbolAddress((void**)&hpre, g_hpre);
    cudaGetSymbolAddress((void**)&agg,  g_agg);
    cudaGetSymbolAddress((void**)&bf,   g_bfrag);
    const uint4* bf_pre = bf;
    const uint4* bf_w1  = bf + 4096;
    const uint4* bf_w2  = bf + 8192;

    cudaFuncSetAttribute(gemm_pre, cudaFuncAttributeMaxDynamicSharedMemorySize, SMEM_TOTAL);
    cudaFuncSetAttribute(gemm_mlp, cudaFuncAttributeMaxDynamicSharedMemorySize, SMEM_TOTAL);

    const int blocks = (N_NODES + TILE_M - 1) / TILE_M;  // 782
    const int eblk   = (N_EDGES + 255) / 256;            // 2344

    // CSR build: hist -> bsum -> offs -> fill (no low-cardinality atomics)
    hist_kernel<<<eblk, 256>>>(dst);
    bsum_kernel<<<196, 256>>>();
    offs_kernel<<<196, 256>>>();
    fill_kernel<<<eblk, 256>>>(src, dst);
    // Weights + pre-projection
    wprep_kernel<<<96, 256>>>(W_pre, W1, W2);
    gemm_pre<<<blocks, NT, SMEM_TOTAL>>>(h, b_pre, bf_pre, hpre, N_NODES);
    // agg[n] = sum of hpre[src] over in-edges (no atomics, warp per node)
    gather_kernel<<<(N_NODES * 32 + 255) / 256, 256>>>(hpre, agg);
    // Fused MLP + residual + LayerNorm
    gemm_mlp<<<blocks, NT, SMEM_TOTAL>>>(agg, b1, b2, bf_w1, bf_w2,
                                         hpre, gamma, beta, out, N_NODES);
    (void)in_sizes; (void)n_in; (void)out_size;
}

// round 13
// speedup vs baseline: 1.8638x; 1.0711x over previous
#include <cuda_runtime.h>
#include <cuda_bf16.h>
#include <math.h>
#include <stdint.h>

#define D_DIM 128
#define N_NODES 50000
#define N_EDGES 600000
#define LN_EPS 1e-5f
#define TILE_M 64
#define NT 256

typedef unsigned int u32;

// Scratch (allocation-free rule: __device__ globals)
__device__ float g_hpre[N_NODES * D_DIM];
__device__ float g_agg [N_NODES * D_DIM];
// Packed W fragments: [w][(ks*16+ni)*32+lane] = {hi0,hi1,lo0,lo1}
__device__ uint4 g_bfrag[3][4096];
// CSR build state. INVARIANT: g_cnt == 0 on entry to kernel_launch
// (static zero-init initially; offs_kernel restores it every call).
__device__ int g_cnt[N_NODES];
__device__ int g_cur[N_NODES];
__device__ int g_off[N_NODES + 1];
__device__ int g_bsum[196];
__device__ int g_csr[N_EDGES];

// Host-side stream/event objects for fork-join capture (created once at
// static init; NOT device memory).
struct StreamKit {
    cudaStream_t csr;
    cudaEvent_t fork, join;
    StreamKit() {
        cudaStreamCreateWithFlags(&csr, cudaStreamNonBlocking);
        cudaEventCreateWithFlags(&fork, cudaEventDisableTiming);
        cudaEventCreateWithFlags(&join, cudaEventDisableTiming);
    }
};
static StreamKit g_sk;

// ---------------- smem layout (bytes) ----------------
#define SM_B1     0
#define SM_B2     512
#define SM_GAMMA  1024
#define SM_BETA   1536
#define SM_RED    2048          // 64 rows x 2 halves x float2 = 1KB
#define SM_AHI    4096          // A frags [ks8][mi4][lane32] x 16B = 16KB
#define SM_ALO    (SM_AHI + 16384)
#define SMEM_TOTAL (SM_ALO + 16384)   // 36864

__device__ __forceinline__ u32 pack_bf16x2(__nv_bfloat16 lo, __nv_bfloat16 hi) {
    __nv_bfloat162 v; v.x = lo; v.y = hi;
    return *(u32*)&v;
}
__device__ __forceinline__ void split2(float a, __nv_bfloat16& hi, __nv_bfloat16& lo) {
    hi = __float2bfloat16_rn(a);
    lo = __float2bfloat16_rn(a - __bfloat162float(hi));
}
__device__ __forceinline__ void mma_bf16(float* c, const u32* a, const u32* b) {
    asm volatile(
        "mma.sync.aligned.m16n8k16.row.col.f32.bf16.bf16.f32 "
        "{%0,%1,%2,%3}, {%4,%5,%6,%7}, {%8,%9}, {%0,%1,%2,%3};"
        : "+f"(c[0]), "+f"(c[1]), "+f"(c[2]), "+f"(c[3])
        : "r"(a[0]), "r"(a[1]), "r"(a[2]), "r"(a[3]), "r"(b[0]), "r"(b[1]));
}

// ---------------------------------------------------------------------------
// W prep: 3 weight matrices -> packed hi/lo B-fragment arrays. 96 CTAs.
// ---------------------------------------------------------------------------
__global__ void wprep_kernel(const float* __restrict__ W0,
                             const float* __restrict__ W1,
                             const float* __restrict__ W2) {
    const float* Ws[3] = {W0, W1, W2};
    int w = blockIdx.x >> 5, part = blockIdx.x & 31;
    const float* W = Ws[w];
    uint4* bf = g_bfrag[w];
    for (int i = part * 256 + threadIdx.x; i < (part + 1) * 256; i += 256) {
        int j = i >> 7, n = i & 127;
        float w0 = W[(size_t)(2 * j)     * 128 + n];
        float w1 = W[(size_t)(2 * j + 1) * 128 + n];
        __nv_bfloat16 h0, l0, h1, l1;
        split2(w0, h0, l0);
        split2(w1, h1, l1);
        int ni = n >> 3, ks = j >> 3;
        int ln = ((n & 7) << 2) | (j & 3);
        int reg = (j >> 2) & 1;
        u32* slot = (u32*)&bf[(ks * 16 + ni) * 32 + ln];
        slot[reg]     = pack_bf16x2(h0, h1);
        slot[2 + reg] = pack_bf16x2(l0, l1);
    }
}

// ---------------------------------------------------------------------------
// CSR build (4 launches): hist -> bsum -> offs -> fill.
// NOTE: NO low-cardinality atomics (600k atomics on 196 addresses serialize
// at the LTS atomic ALU and cost ~75us — measured in rounds 10/11).
// ---------------------------------------------------------------------------
__global__ void hist_kernel(const int* __restrict__ dst) {
    int e = blockIdx.x * blockDim.x + threadIdx.x;
    if (e < N_EDGES) atomicAdd(&g_cnt[dst[e]], 1);   // 50k addresses: OK
}
__global__ void bsum_kernel() {   // block b sums g_cnt[b*256 .. b*256+256)
    __shared__ int s[256];
    int n = blockIdx.x * 256 + threadIdx.x;
    s[threadIdx.x] = (n < N_NODES) ? g_cnt[n] : 0;
    __syncthreads();
    #pragma unroll
    for (int w = 128; w > 0; w >>= 1) {
        if (threadIdx.x < w) s[threadIdx.x] += s[threadIdx.x + w];
        __syncthreads();
    }
    if (threadIdx.x == 0) g_bsum[blockIdx.x] = s[0];
}
__global__ void offs_kernel() {
    __shared__ int wsum[8];
    __shared__ int bpref_s;
    int b = blockIdx.x, t = threadIdx.x;
    int n = b * 256 + t;
    // block prefix: sum of g_bsum[0..b), one warp
    if (t < 32) {
        int s = 0;
        for (int i = t; i < b; i += 32) s += g_bsum[i];
        #pragma unroll
        for (int o = 16; o; o >>= 1) s += __shfl_xor_sync(0xFFFFFFFFu, s, o);
        if (t == 0) bpref_s = s;
    }
    int cnt = (n < N_NODES) ? g_cnt[n] : 0;
    if (n < N_NODES) g_cnt[n] = 0;        // restore invariant for next call
    // warp inclusive scan
    int x = cnt;
    #pragma unroll
    for (int o = 1; o < 32; o <<= 1) {
        int y = __shfl_up_sync(0xFFFFFFFFu, x, o);
        if ((t & 31) >= o) x += y;
    }
    if ((t & 31) == 31) wsum[t >> 5] = x;
    __syncthreads();
    if (t < 8) {
        int v = wsum[t];
        #pragma unroll
        for (int o = 1; o < 8; o <<= 1) {
            int y = __shfl_up_sync(0xFFu, v, o);
            if (t >= o) v += y;
        }
        wsum[t] = v;
    }
    __syncthreads();
    int wpref = (t >= 32) ? wsum[(t >> 5) - 1] : 0;
    int off = bpref_s + wpref + x - cnt;   // exclusive prefix
    if (n < N_NODES) { g_off[n] = off; g_cur[n] = off; }
    if (b == 195 && t == 255) g_off[N_NODES] = N_EDGES;
}
__global__ void fill_kernel(const int* __restrict__ src,
                            const int* __restrict__ dst) {
    int e = blockIdx.x * blockDim.x + threadIdx.x;
    if (e < N_EDGES) {
        int p = atomicAdd(&g_cur[dst[e]], 1);
        g_csr[p] = src[e];
    }
}

// ---------------------------------------------------------------------------
// Gather-sum: one warp per node, no atomics, 4-way edge unroll.
// ---------------------------------------------------------------------------
__global__ void gather_kernel(const float* __restrict__ hpre,
                              float* __restrict__ agg) {
    int gid  = blockIdx.x * blockDim.x + threadIdx.x;
    int node = gid >> 5;
    int lane = gid & 31;
    if (node >= N_NODES) return;
    int e0 = g_off[node], e1 = g_off[node + 1];
    float4 acc = make_float4(0.f, 0.f, 0.f, 0.f);
    const float4* h4 = (const float4*)hpre;
    int e = e0;
    for (; e + 3 < e1; e += 4) {
        int s0 = g_csr[e],     s1 = g_csr[e + 1];
        int s2 = g_csr[e + 2], s3 = g_csr[e + 3];
        float4 v0 = __ldg(&h4[(size_t)s0 * 32 + lane]);
        float4 v1 = __ldg(&h4[(size_t)s1 * 32 + lane]);
        float4 v2 = __ldg(&h4[(size_t)s2 * 32 + lane]);
        float4 v3 = __ldg(&h4[(size_t)s3 * 32 + lane]);
        acc.x += (v0.x + v1.x) + (v2.x + v3.x);
        acc.y += (v0.y + v1.y) + (v2.y + v3.y);
        acc.z += (v0.z + v1.z) + (v2.z + v3.z);
        acc.w += (v0.w + v1.w) + (v2.w + v3.w);
    }
    for (; e < e1; e++) {
        float4 v = __ldg(&h4[(size_t)g_csr[e] * 32 + lane]);
        acc.x += v.x; acc.y += v.y; acc.z += v.z; acc.w += v.w;
    }
    ((float4*)agg)[(size_t)node * 32 + lane] = acc;
}

// ---------------------------------------------------------------------------
// GEMM building blocks: TILE_M=64, 256 threads, 8 warps = (m 0..3, n 0..1)
// ---------------------------------------------------------------------------
__device__ __forceinline__ void stage_A(char* smem, const float* __restrict__ A,
                                        int base, int nrows, int tid) {
    const float2* A2 = (const float2*)A;
    #pragma unroll 4
    for (int i = tid; i < TILE_M * 64; i += NT) {
        int row = i >> 6, j = i & 63;
        float2 a = (base + row < nrows) ? A2[(size_t)(base + row) * 64 + j]
                                        : make_float2(0.f, 0.f);
        __nv_bfloat16 hx, lx, hy, ly;
        split2(a.x, hx, lx);
        split2(a.y, hy, ly);
        int mi = row >> 4, ks = j >> 3;
        int ln = ((row & 7) << 2) | (j & 3);
        int reg = (((j >> 2) & 1) << 1) | ((row >> 3) & 1);
        int off = ((ks * 4 + mi) * 32 + ln) * 16 + reg * 4;
        *(u32*)(smem + SM_AHI + off) = pack_bf16x2(hx, hy);
        *(u32*)(smem + SM_ALO + off) = pack_bf16x2(lx, ly);
    }
}

__device__ __forceinline__ void mma_mainloop(const char* smem,
                                             const uint4* __restrict__ bf,
                                             float c[8][4],
                                             int wid_m, int wid_n, int lane) {
    #pragma unroll
    for (int ks = 0; ks < 8; ks++) {
        u32 ah[4], al[4];
        *(uint4*)ah = *(const uint4*)(smem + SM_AHI + ((ks * 4 + wid_m) * 32 + lane) * 16);
        *(uint4*)al = *(const uint4*)(smem + SM_ALO + ((ks * 4 + wid_m) * 32 + lane) * 16);
        #pragma unroll
        for (int q = 0; q < 8; q++) {
            uint4 v = __ldg(&bf[(ks * 16 + wid_n * 8 + q) * 32 + lane]);
            u32 bh[2] = {v.x, v.y};
            u32 bl[2] = {v.z, v.w};
            mma_bf16(c[q], ah, bh);   // Ah*Bh
            mma_bf16(c[q], al, bh);   // Al*Bh
            mma_bf16(c[q], ah, bl);   // Ah*Bl
        }
    }
}

// ---------------------------------------------------------------------------
// gemm_pre: hpre = A @ W_pre + b_pre
// ---------------------------------------------------------------------------
__global__ void __launch_bounds__(NT, 2)
gemm_pre(const float* __restrict__ A, const float* __restrict__ bias,
         const uint4* __restrict__ bf, float* __restrict__ out, int nrows) {
    extern __shared__ char smem[];
    const int tid = threadIdx.x, wid = tid >> 5, lane = tid & 31;
    const int wid_m = wid >> 1, wid_n = wid & 1;
    const int base = blockIdx.x * TILE_M;

    float* bias_s = (float*)(smem + SM_B1);
    if (tid < 128) bias_s[tid] = bias[tid];
    stage_A(smem, A, base, nrows, tid);
    __syncthreads();

    float c[8][4];
    #pragma unroll
    for (int q = 0; q < 8; q++)
        #pragma unroll
        for (int r = 0; r < 4; r++) c[q][r] = 0.f;

    mma_mainloop(smem, bf, c, wid_m, wid_n, lane);

    const int g = lane >> 2, t = lane & 3;
    const int row0 = base + wid_m * 16 + g, row1 = row0 + 8;
    const bool ok0 = row0 < nrows, ok1 = row1 < nrows;
    float2* out2 = (float2*)out;
    #pragma unroll
    for (int q = 0; q < 8; q++) {
        int col = (wid_n * 8 + q) * 8 + t * 2;
        float2 b2 = *(const float2*)(bias_s + col);
        if (ok0) out2[(size_t)row0 * 64 + (col >> 1)] =
            make_float2(c[q][0] + b2.x, c[q][1] + b2.y);
        if (ok1) out2[(size_t)row1 * 64 + (col >> 1)] =
            make_float2(c[q][2] + b2.x, c[q][3] + b2.y);
    }
}

// ---------------------------------------------------------------------------
// gemm_mlp: out = LayerNorm(resid + relu(relu(A@W1+b1)@W2+b2)) * gamma + beta
// ---------------------------------------------------------------------------
__global__ void __launch_bounds__(NT, 2)
gemm_mlp(const float* __restrict__ A,
         const float* __restrict__ b1v, const float* __restrict__ b2v,
         const uint4* __restrict__ bf1, const uint4* __restrict__ bf2,
         const float* __restrict__ resid,
         const float* __restrict__ gamma, const float* __restrict__ beta,
         float* __restrict__ out, int nrows) {
    extern __shared__ char smem[];
    const int tid = threadIdx.x, wid = tid >> 5, lane = tid & 31;
    const int wid_m = wid >> 1, wid_n = wid & 1;
    const int base = blockIdx.x * TILE_M;

    float* b1_s = (float*)(smem + SM_B1);
    float* b2_s = (float*)(smem + SM_B2);
    float* gm_s = (float*)(smem + SM_GAMMA);
    float* bt_s = (float*)(smem + SM_BETA);
    float2* red = (float2*)(smem + SM_RED);
    if (tid < 128) {
        b1_s[tid] = b1v[tid];
        b2_s[tid] = b2v[tid];
        gm_s[tid] = gamma[tid];
        bt_s[tid] = beta[tid];
    }
    stage_A(smem, A, base, nrows, tid);
    __syncthreads();

    float c[8][4];
    #pragma unroll
    for (int q = 0; q < 8; q++)
        #pragma unroll
        for (int r = 0; r < 4; r++) c[q][r] = 0.f;

    // ---- GEMM 1: c = A @ W1 ----
    mma_mainloop(smem, bf1, c, wid_m, wid_n, lane);

    __syncthreads();   // all warps done reading A-frags before overwrite

    // ---- Convert t1 = relu(c + b1) into A-frag smem (in-lane mapping) ----
    const int g = lane >> 2, t = lane & 3;
    {
        #pragma unroll
        for (int q2 = 0; q2 < 4; q2++) {
            int ks = wid_n * 4 + q2;
            u32 vh[4], vl[4];
            #pragma unroll
            for (int half = 0; half < 2; half++) {
                int q = 2 * q2 + half;
                int col = (wid_n * 8 + q) * 8 + t * 2;
                float2 b2 = *(const float2*)(b1_s + col);
                float v00 = fmaxf(c[q][0] + b2.x, 0.f);
                float v01 = fmaxf(c[q][1] + b2.y, 0.f);
                float v10 = fmaxf(c[q][2] + b2.x, 0.f);
                float v11 = fmaxf(c[q][3] + b2.y, 0.f);
                __nv_bfloat16 h00, l00, h01, l01, h10, l10, h11, l11;
                split2(v00, h00, l00); split2(v01, h01, l01);
                split2(v10, h10, l10); split2(v11, h11, l11);
                vh[half * 2 + 0] = pack_bf16x2(h00, h01);
                vh[half * 2 + 1] = pack_bf16x2(h10, h11);
                vl[half * 2 + 0] = pack_bf16x2(l00, l01);
                vl[half * 2 + 1] = pack_bf16x2(l10, l11);
            }
            int off = ((ks * 4 + wid_m) * 32 + lane) * 16;
            *(uint4*)(smem + SM_AHI + off) = *(uint4*)vh;
            *(uint4*)(smem + SM_ALO + off) = *(uint4*)vl;
        }
    }
    __syncthreads();

    #pragma unroll
    for (int q = 0; q < 8; q++)
        #pragma unroll
        for (int r = 0; r < 4; r++) c[q][r] = 0.f;

    // ---- GEMM 2: c = t1 @ W2 ----
    mma_mainloop(smem, bf2, c, wid_m, wid_n, lane);

    // ---- Epilogue: v = resid + relu(c + b2); out = LN(v)*gamma + beta ----
    const int row0 = base + wid_m * 16 + g, row1 = row0 + 8;
    const int lr0 = wid_m * 16 + g, lr1 = lr0 + 8;
    const bool ok0 = row0 < nrows, ok1 = row1 < nrows;
    const float2* R2 = (const float2*)resid;
    float s0 = 0.f, q0 = 0.f, s1 = 0.f, q1 = 0.f;
    #pragma unroll
    for (int q = 0; q < 8; q++) {
        int col = (wid_n * 8 + q) * 8 + t * 2;
        float2 b2 = *(const float2*)(b2_s + col);
        float2 r0 = ok0 ? R2[(size_t)row0 * 64 + (col >> 1)] : make_float2(0.f, 0.f);
        float2 r1 = ok1 ? R2[(size_t)row1 * 64 + (col >> 1)] : make_float2(0.f, 0.f);
        float v00 = fmaxf(c[q][0] + b2.x, 0.f) + r0.x;
        float v01 = fmaxf(c[q][1] + b2.y, 0.f) + r0.y;
        float v10 = fmaxf(c[q][2] + b2.x, 0.f) + r1.x;
        float v11 = fmaxf(c[q][3] + b2.y, 0.f) + r1.y;
        c[q][0] = v00; c[q][1] = v01; c[q][2] = v10; c[q][3] = v11;
        s0 += v00 + v01; q0 += v00 * v00 + v01 * v01;
        s1 += v10 + v11; q1 += v10 * v10 + v11 * v11;
    }
    #pragma unroll
    for (int off = 1; off <= 2; off <<= 1) {
        s0 += __shfl_xor_sync(0xFFFFFFFFu, s0, off);
        q0 += __shfl_xor_sync(0xFFFFFFFFu, q0, off);
        s1 += __shfl_xor_sync(0xFFFFFFFFu, s1, off);
        q1 += __shfl_xor_sync(0xFFFFFFFFu, q1, off);
    }
    if (t == 0) {
        red[lr0 * 2 + wid_n] = make_float2(s0, q0);
        red[lr1 * 2 + wid_n] = make_float2(s1, q1);
    }
    __syncthreads();
    {
        float2 a0 = red[lr0 * 2 + 0], a1 = red[lr0 * 2 + 1];
        float2 c0 = red[lr1 * 2 + 0], c1 = red[lr1 * 2 + 1];
        s0 = a0.x + a1.x; q0 = a0.y + a1.y;
        s1 = c0.x + c1.x; q1 = c0.y + c1.y;
    }
    float mean0 = s0 * (1.0f / D_DIM);
    float mean1 = s1 * (1.0f / D_DIM);
    float rstd0 = rsqrtf(q0 * (1.0f / D_DIM) - mean0 * mean0 + LN_EPS);
    float rstd1 = rsqrtf(q1 * (1.0f / D_DIM) - mean1 * mean1 + LN_EPS);
    float2* out2 = (float2*)out;
    #pragma unroll
    for (int q = 0; q < 8; q++) {
        int col = (wid_n * 8 + q) * 8 + t * 2;
        float2 g2 = *(const float2*)(gm_s + col);
        float2 t2 = *(const float2*)(bt_s + col);
        if (ok0) {
            float2 o;
            o.x = (c[q][0] - mean0) * rstd0 * g2.x + t2.x;
            o.y = (c[q][1] - mean0) * rstd0 * g2.y + t2.y;
            out2[(size_t)row0 * 64 + (col >> 1)] = o;
        }
        if (ok1) {
            float2 o;
            o.x = (c[q][2] - mean1) * rstd1 * g2.x + t2.x;
            o.y = (c[q][3] - mean1) * rstd1 * g2.y + t2.y;
            out2[(size_t)row1 * 64 + (col >> 1)] = o;
        }
    }
}

// ---------------------------------------------------------------------------
extern "C" void kernel_launch(void* const* d_in, const int* in_sizes, int n_in,
                              void* d_out, int out_size) {
    const float* h     = (const float*)d_in[0];
    const int*   src   = (const int*)  d_in[1];
    const int*   dst   = (const int*)  d_in[2];
    const float* W_pre = (const float*)d_in[3];
    const float* b_pre = (const float*)d_in[4];
    const float* W1    = (const float*)d_in[5];
    const float* b1    = (const float*)d_in[6];
    const float* W2    = (const float*)d_in[7];
    const float* b2    = (const float*)d_in[8];
    const float* gamma = (const float*)d_in[9];
    const float* beta  = (const float*)d_in[10];
    float* out = (float*)d_out;

    float *hpre, *agg;
    uint4* bf;
    cudaGetSymbolAddress((void**)&hpre, g_hpre);
    cudaGetSymbolAddress((void**)&agg,  g_agg);
    cudaGetSymbolAddress((void**)&bf,   g_bfrag);
    const uint4* bf_pre = bf;
    const uint4* bf_w1  = bf + 4096;
    const uint4* bf_w2  = bf + 8192;

    cudaFuncSetAttribute(gemm_pre, cudaFuncAttributeMaxDynamicSharedMemorySize, SMEM_TOTAL);
    cudaFuncSetAttribute(gemm_mlp, cudaFuncAttributeMaxDynamicSharedMemorySize, SMEM_TOTAL);

    const int blocks = (N_NODES + TILE_M - 1) / TILE_M;  // 782
    const int eblk   = (N_EDGES + 255) / 256;            // 2344

    // Fork: CSR chain on side stream, overlapped with wprep+gemm_pre.
    cudaEventRecord(g_sk.fork, 0);
    cudaStreamWaitEvent(g_sk.csr, g_sk.fork, 0);

    // Chain B (side stream): hist -> bsum -> offs -> fill
    hist_kernel<<<eblk, 256, 0, g_sk.csr>>>(dst);
    bsum_kernel<<<196, 256, 0, g_sk.csr>>>();
    offs_kernel<<<196, 256, 0, g_sk.csr>>>();
    fill_kernel<<<eblk, 256, 0, g_sk.csr>>>(src, dst);
    cudaEventRecord(g_sk.join, g_sk.csr);

    // Chain A (main stream): weights + pre-projection
    wprep_kernel<<<96, 256>>>(W_pre, W1, W2);
    gemm_pre<<<blocks, NT, SMEM_TOTAL>>>(h, b_pre, bf_pre, hpre, N_NODES);

    // Join: gather needs both hpre (A) and csr (B)
    cudaStreamWaitEvent(0, g_sk.join, 0);
    gather_kernel<<<(N_NODES * 32 + 255) / 256, 256>>>(hpre, agg);
    // Fused MLP + residual + LayerNorm
    gemm_mlp<<<blocks, NT, SMEM_TOTAL>>>(agg, b1, b2, bf_w1, bf_w2,
                                         hpre, gamma, beta, out, N_NODES);
    (void)in_sizes; (void)n_in; (void)out_size;
}